// round 14
// baseline (speedup 1.0000x reference)
#include <cuda_runtime.h>
#include <cuda_fp16.h>
#include <math.h>
#include <stdint.h>

#define N_NODES 100000
#define D_FEAT  128
#define E_EDGES 600000
#define C_OUT   256

// ---------------- scratch (no allocs allowed; __device__ globals) -------------
__device__ __align__(16) float  g_sums[(size_t)N_NODES * D_FEAT];  // 51.2 MB
__device__ __align__(16) __half g_x16[(size_t)N_NODES * D_FEAT];   // 25.6 MB
__device__ float g_cnt[N_NODES];
__device__ int   g_idx64;
// W pre-transposed, fp16: [n][k] rows of 256 fp16 (512B)
__device__ __align__(16) unsigned char g_B16_t[256 * 512];

// ---------------- merged init: zero + x->fp16 + W prep + idx detect ----------
// blocks [0,12500): zero sums/cnt. [12500,25000): convert x. [25000,25256): W.
#define ZBLKS 12500
#define XBLKS 12500
__global__ void init_kernel(const float* __restrict__ x,
                            const float* __restrict__ W,
                            const long long* __restrict__ ei) {
    if (blockIdx.x < ZBLKS) {
        int i = blockIdx.x * 256 + threadIdx.x;
        const int TOT4 = N_NODES * D_FEAT / 4;
        if (i < TOT4) reinterpret_cast<float4*>(g_sums)[i] = make_float4(0.f, 0.f, 0.f, 0.f);
        if (i < N_NODES) g_cnt[i] = 0.f;
    } else if (blockIdx.x < ZBLKS + XBLKS) {
        int i = (blockIdx.x - ZBLKS) * 256 + threadIdx.x;   // float4 index
        const int TOT4 = N_NODES * D_FEAT / 4;
        if (i < TOT4) {
            float4 v = reinterpret_cast<const float4*>(x)[i];
            __half2 h0 = __floats2half2_rn(v.x, v.y);
            __half2 h1 = __floats2half2_rn(v.z, v.w);
            uint2 pk;
            pk.x = *reinterpret_cast<uint32_t*>(&h0);
            pk.y = *reinterpret_cast<uint32_t*>(&h1);
            reinterpret_cast<uint2*>(g_x16)[i] = pk;
        }
    } else {
        int k = blockIdx.x - ZBLKS - XBLKS;  // 0..255
        int n = threadIdx.x;                 // 0..255
        float w = W[k * C_OUT + n];
        reinterpret_cast<__half*>(g_B16_t)[n * 256 + k] = __float2half_rn(w);
        if (k == 0 && n == 0) {
            int ok = 1;
#pragma unroll
            for (int i = 0; i < 8; i++) {
                long long v = ei[i];
                if (v < 0 || v >= (long long)N_NODES) ok = 0;
            }
            g_idx64 = ok;
        }
    }
}

// ---------------- vector reduction helper ------------------------------------
__device__ __forceinline__ void red_add_v4(float* p, float4 v) {
    asm volatile("red.global.add.v4.f32 [%0], {%1, %2, %3, %4};"
                 :: "l"(p), "f"(v.x), "f"(v.y), "f"(v.z), "f"(v.w) : "memory");
}

// ---------------- edge scatter: 4 edges/warp, fp16 gather, fp32 RED ----------
#define EPW 4
__global__ void scatter_kernel(const long long* __restrict__ ei) {
    const int warp = (blockIdx.x * blockDim.x + threadIdx.x) >> 5;
    const int lane = threadIdx.x & 31;
    const int e0 = warp * EPW;
    if (e0 >= E_EDGES) return;

    const int use64 = g_idx64;
    int r[EPW], c[EPW];
#pragma unroll
    for (int i = 0; i < EPW; i++) {
        int e = e0 + i;                      // E_EDGES % EPW == 0
        if (use64) {
            r[i] = (int)ei[e];
            c[i] = (int)ei[E_EDGES + e];
        } else {
            const int* p = (const int*)ei;
            r[i] = p[e];
            c[i] = p[E_EDGES + e];
        }
    }

    // fp16 gathers: 8B/lane (4 features), independent -> MLP=EPW
    uint2 h[EPW];
#pragma unroll
    for (int i = 0; i < EPW; i++)
        if (r[i] != c[i])
            h[i] = *reinterpret_cast<const uint2*>(g_x16 + (size_t)c[i] * D_FEAT + lane * 4);

#pragma unroll
    for (int i = 0; i < EPW; i++) {
        if (r[i] != c[i]) {
            float2 f0 = __half22float2(*reinterpret_cast<__half2*>(&h[i].x));
            float2 f1 = __half22float2(*reinterpret_cast<__half2*>(&h[i].y));
            float4 v = make_float4(f0.x, f0.y, f1.x, f1.y);
            red_add_v4(g_sums + (size_t)r[i] * D_FEAT + lane * 4, v);
            if (lane == 0) atomicAdd(&g_cnt[r[i]], 1.0f);
        }
    }
}

// ---------------- HMMA GEMM: (mean||x) @ W + bias + row-L2-normalize ---------
// BM=128, BN=256, 512 threads = 16 warps as 4(M)x4(N); warp tile 32x64.
// mma.sync m16n8k16 fp16->f32, single pass. ldmatrix.x4 fragment loads.
// smem rows padded to 272B (136 fp16): conflict-free.
#define BMROWS 128
#define ROWB 272
#define ROWH 136
#define SM_BIAS 0
#define SM_RED  1024
#define SM_A    4096
#define SM_B    (SM_A + BMROWS * ROWB)     // 38912
#define SM_TOT  (SM_B + 256 * ROWB)        // 108544

__device__ __forceinline__ void mma16816(float d[4], const uint32_t a[4], const uint32_t b[2]) {
    asm volatile("mma.sync.aligned.m16n8k16.row.col.f32.f16.f16.f32 "
                 "{%0,%1,%2,%3}, {%4,%5,%6,%7}, {%8,%9}, {%0,%1,%2,%3};"
                 : "+f"(d[0]), "+f"(d[1]), "+f"(d[2]), "+f"(d[3])
                 : "r"(a[0]), "r"(a[1]), "r"(a[2]), "r"(a[3]), "r"(b[0]), "r"(b[1]));
}

__device__ __forceinline__ void ldsm_x4(uint32_t r[4], uint32_t addr) {
    asm volatile("ldmatrix.sync.aligned.m8n8.x4.shared.b16 {%0,%1,%2,%3}, [%4];"
                 : "=r"(r[0]), "=r"(r[1]), "=r"(r[2]), "=r"(r[3]) : "r"(addr));
}

__global__ void __launch_bounds__(512, 1) gemm_hmma_kernel(const float* __restrict__ bias,
                                                           float* __restrict__ out) {
    extern __shared__ __align__(16) unsigned char smem[];
    const uint32_t smb = (uint32_t)__cvta_generic_to_shared(smem);
    const int tid = threadIdx.x;
    const int wid = tid >> 5;
    const int lid = tid & 31;
    const int wm  = wid >> 2;            // 0..3 : rows wm*32..+31
    const int wn  = wid & 3;             // 0..3 : cols wn*64..+63
    const int r4  = lid >> 2;            // 0..7
    const int c4  = lid & 3;             // 0..3
    const int node0 = blockIdx.x * BMROWS;

    // ldmatrix per-lane source rows/k-offsets
    const int a_lrow = (lid & 7) + ((lid & 8)  ? 8 : 0);
    const int a_lko  = (lid & 16) ? 8 : 0;
    const int b_lrow = (lid & 7) + ((lid & 16) ? 8 : 0);
    const int b_lko  = (lid & 8) ? 8 : 0;

    // stage bias
    if (tid < 256) reinterpret_cast<float*>(smem + SM_BIAS)[tid] = bias[tid];

    // A staging role: row = tid>>2 (0..127), k-base = (tid&3)*32 within 128-chunk
    const int arow = tid >> 2;
    const int akb  = (tid & 3) * 32;
    const int amg  = node0 + arow;
    const bool a_ok = (amg < N_NODES);
    const float inv_cnt = a_ok ? (1.0f / fmaxf(g_cnt[amg], 1.0f)) : 0.f;

    float acc[2][8][4];
#pragma unroll
    for (int mt = 0; mt < 2; mt++)
#pragma unroll
        for (int nt = 0; nt < 8; nt++)
#pragma unroll
            for (int q = 0; q < 4; q++) acc[mt][nt][q] = 0.f;

    const uint4* gb = reinterpret_cast<const uint4*>(g_B16_t);

#pragma unroll 1
    for (int c = 0; c < 2; c++) {
        // ---- stage A ----
        if (c == 0) {
            // mean chunk: fp32 sums * inv_cnt -> fp16
            const float* asrc = g_sums + (size_t)amg * D_FEAT + akb;
#pragma unroll
            for (int q = 0; q < 8; q++) {
                float4 v = make_float4(0.f, 0.f, 0.f, 0.f);
                if (a_ok) {
                    v = *reinterpret_cast<const float4*>(asrc + q * 4);
                    v.x *= inv_cnt; v.y *= inv_cnt; v.z *= inv_cnt; v.w *= inv_cnt;
                }
                __half2 h0 = __floats2half2_rn(v.x, v.y);
                __half2 h1 = __floats2half2_rn(v.z, v.w);
                uint32_t byt = (uint32_t)(arow * ROWH + akb + q * 4) * 2;
                *reinterpret_cast<uint32_t*>(smem + SM_A + byt)     = *reinterpret_cast<uint32_t*>(&h0);
                *reinterpret_cast<uint32_t*>(smem + SM_A + byt + 4) = *reinterpret_cast<uint32_t*>(&h1);
            }
        } else {
            // x chunk: straight fp16 copy (identical bits to prior conversion)
            const __half* hx = g_x16 + (size_t)amg * D_FEAT + akb;
            uint32_t byt = (uint32_t)(arow * ROWH + akb) * 2;
#pragma unroll
            for (int j = 0; j < 4; j++) {
                uint4 hv = make_uint4(0u, 0u, 0u, 0u);
                if (a_ok) hv = *reinterpret_cast<const uint4*>(hx + j * 8);
                *reinterpret_cast<uint4*>(smem + SM_A + byt + j * 16) = hv;
            }
        }
        // ---- stage B (coalesced copy of 128-fp16 slices) ----
#pragma unroll
        for (int i = 0; i < 8; i++) {
            int f = i * 512 + tid;           // 0..4095
            int n = f >> 4;
            int j = f & 15;
            *reinterpret_cast<uint4*>(smem + SM_B + n * ROWB + j * 16) = gb[n * 32 + c * 16 + j];
        }
        __syncthreads();

        // ---- compute: 8 k-steps of 16 ----
#pragma unroll
        for (int ks = 0; ks < 8; ks++) {
            const int kb = ks * 16;
            uint32_t af[2][4];
#pragma unroll
            for (int mt = 0; mt < 2; mt++) {
                uint32_t ao = smb + (uint32_t)((wm * 32 + mt * 16 + a_lrow) * ROWH + kb + a_lko) * 2;
                ldsm_x4(af[mt], SM_A + ao);
            }
            uint32_t bf[4][4];
#pragma unroll
            for (int np = 0; np < 4; np++) {
                uint32_t bo = smb + (uint32_t)((wn * 64 + np * 16 + b_lrow) * ROWH + kb + b_lko) * 2;
                ldsm_x4(bf[np], SM_B + bo);
            }
#pragma unroll
            for (int mt = 0; mt < 2; mt++)
#pragma unroll
                for (int nt = 0; nt < 8; nt++)
                    mma16816(acc[mt][nt], af[mt], &bf[nt >> 1][(nt & 1) * 2]);
        }
        __syncthreads();
    }

    // ---- epilogue: + bias, row L2 norm, store ----
    const float* bsm = reinterpret_cast<const float*>(smem + SM_BIAS);
    float ssq[2][2] = {{0.f, 0.f}, {0.f, 0.f}};
#pragma unroll
    for (int mt = 0; mt < 2; mt++)
#pragma unroll
        for (int nt = 0; nt < 8; nt++) {
            int col = wn * 64 + nt * 8 + 2 * c4;
            float b0 = bsm[col], b1 = bsm[col + 1];
            float* d = acc[mt][nt];
            d[0] += b0; d[1] += b1; d[2] += b0; d[3] += b1;
            ssq[mt][0] += d[0] * d[0] + d[1] * d[1];
            ssq[mt][1] += d[2] * d[2] + d[3] * d[3];
        }
#pragma unroll
    for (int off = 1; off <= 2; off <<= 1) {
        ssq[0][0] += __shfl_xor_sync(0xFFFFFFFFu, ssq[0][0], off);
        ssq[0][1] += __shfl_xor_sync(0xFFFFFFFFu, ssq[0][1], off);
        ssq[1][0] += __shfl_xor_sync(0xFFFFFFFFu, ssq[1][0], off);
        ssq[1][1] += __shfl_xor_sync(0xFFFFFFFFu, ssq[1][1], off);
    }
    float* rp = reinterpret_cast<float*>(smem + SM_RED);   // [4 warps_n][128 rows]
    if (c4 == 0) {
#pragma unroll
        for (int mt = 0; mt < 2; mt++)
#pragma unroll
            for (int h = 0; h < 2; h++)
                rp[wn * BMROWS + wm * 32 + mt * 16 + r4 + 8 * h] = ssq[mt][h];
    }
    __syncthreads();

#pragma unroll
    for (int mt = 0; mt < 2; mt++)
#pragma unroll
        for (int h = 0; h < 2; h++) {
            int rr = wm * 32 + mt * 16 + r4 + 8 * h;
            float s = rp[rr] + rp[BMROWS + rr] + rp[2 * BMROWS + rr] + rp[3 * BMROWS + rr];
            float invn = 1.0f / fmaxf(sqrtf(s), 1e-12f);
            int row = node0 + rr;
            if (row < N_NODES) {
#pragma unroll
                for (int nt = 0; nt < 8; nt++) {
                    float* d = acc[mt][nt];
                    float2 o;
                    o.x = d[2 * h]     * invn;
                    o.y = d[2 * h + 1] * invn;
                    *reinterpret_cast<float2*>(out + (size_t)row * C_OUT + wn * 64 + nt * 8 + 2 * c4) = o;
                }
            }
        }
}

// ---------------- launch ------------------------------------------------------
extern "C" void kernel_launch(void* const* d_in, const int* in_sizes, int n_in,
                              void* d_out, int out_size) {
    const float*     x    = (const float*)d_in[0];      // [100000,128]
    const long long* ei   = (const long long*)d_in[1];  // [2,600000]
    const float*     W    = (const float*)d_in[2];      // [256,256]
    const float*     bias = (const float*)d_in[3];      // [1,256]
    float*           out  = (float*)d_out;              // [100000,256]

    init_kernel<<<ZBLKS + XBLKS + 256, 256>>>(x, W, ei);

    {
        long long threads = (long long)(E_EDGES / EPW) * 32;
        scatter_kernel<<<(int)((threads + 255) / 256), 256>>>(ei);
    }

    {
        cudaFuncSetAttribute(gemm_hmma_kernel, cudaFuncAttributeMaxDynamicSharedMemorySize, SM_TOT);
        int grid = (N_NODES + BMROWS - 1) / BMROWS;     // 782
        gemm_hmma_kernel<<<grid, 512, SM_TOT>>>(bias, out);
    }
}

// round 15
// speedup vs baseline: 1.2778x; 1.2778x over previous
#include <cuda_runtime.h>
#include <cuda_fp16.h>
#include <math.h>
#include <stdint.h>

#define N_NODES 100000
#define D_FEAT  128
#define E_EDGES 600000
#define C_OUT   256

// ---------------- scratch (no allocs allowed; __device__ globals) -------------
__device__ __align__(16) __half g_sums16[(size_t)N_NODES * D_FEAT]; // 25.6 MB fp16 accumulators
__device__ __align__(16) __half g_x16[(size_t)N_NODES * D_FEAT];    // 25.6 MB fp16 x image
__device__ float g_cnt[N_NODES];
__device__ int   g_idx64;
// W pre-transposed, fp16: [n][k] rows of 256 fp16 (512B)
__device__ __align__(16) unsigned char g_B16_t[256 * 512];

// ---------------- merged init: zero + x->fp16 + W prep + idx detect ----------
// blocks [0,6250): zero sums16/cnt. [6250,18750): convert x. [18750,19006): W.
#define ZBLKS 6250
#define XBLKS 12500
__global__ void init_kernel(const float* __restrict__ x,
                            const float* __restrict__ W,
                            const long long* __restrict__ ei) {
    if (blockIdx.x < ZBLKS) {
        int i = blockIdx.x * 256 + threadIdx.x;              // uint4 index
        const int TOTH4 = N_NODES * D_FEAT * 2 / 16;         // 1.6M
        if (i < TOTH4) reinterpret_cast<uint4*>(g_sums16)[i] = make_uint4(0u, 0u, 0u, 0u);
        if (i < N_NODES) g_cnt[i] = 0.f;
    } else if (blockIdx.x < ZBLKS + XBLKS) {
        int i = (blockIdx.x - ZBLKS) * 256 + threadIdx.x;    // float4 index
        const int TOT4 = N_NODES * D_FEAT / 4;
        if (i < TOT4) {
            float4 v = reinterpret_cast<const float4*>(x)[i];
            __half2 h0 = __floats2half2_rn(v.x, v.y);
            __half2 h1 = __floats2half2_rn(v.z, v.w);
            uint2 pk;
            pk.x = *reinterpret_cast<uint32_t*>(&h0);
            pk.y = *reinterpret_cast<uint32_t*>(&h1);
            reinterpret_cast<uint2*>(g_x16)[i] = pk;
        }
    } else {
        int k = blockIdx.x - ZBLKS - XBLKS;  // 0..255
        int n = threadIdx.x;                 // 0..255
        float w = W[k * C_OUT + n];
        reinterpret_cast<__half*>(g_B16_t)[n * 256 + k] = __float2half_rn(w);
        if (k == 0 && n == 0) {
            int ok = 1;
#pragma unroll
            for (int i = 0; i < 8; i++) {
                long long v = ei[i];
                if (v < 0 || v >= (long long)N_NODES) ok = 0;
            }
            g_idx64 = ok;
        }
    }
}

// ---------------- fp16x2 vector reduction ------------------------------------
__device__ __forceinline__ void red_add_h2x2(__half* p, uint2 v) {
    asm volatile("red.global.add.noftz.v2.f16x2 [%0], {%1, %2};"
                 :: "l"(p), "r"(v.x), "r"(v.y) : "memory");
}

// ---------------- edge scatter: 4 edges/warp, pure fp16 gather+RED -----------
#define EPW 4
__global__ void scatter_kernel(const long long* __restrict__ ei) {
    const int warp = (blockIdx.x * blockDim.x + threadIdx.x) >> 5;
    const int lane = threadIdx.x & 31;
    const int e0 = warp * EPW;
    if (e0 >= E_EDGES) return;

    const int use64 = g_idx64;
    int r[EPW], c[EPW];
#pragma unroll
    for (int i = 0; i < EPW; i++) {
        int e = e0 + i;                      // E_EDGES % EPW == 0
        if (use64) {
            r[i] = (int)ei[e];
            c[i] = (int)ei[E_EDGES + e];
        } else {
            const int* p = (const int*)ei;
            r[i] = p[e];
            c[i] = p[E_EDGES + e];
        }
    }

    // fp16 gathers: 8B/lane (4 features), independent -> MLP=EPW
    uint2 h[EPW];
#pragma unroll
    for (int i = 0; i < EPW; i++)
        if (r[i] != c[i])
            h[i] = *reinterpret_cast<const uint2*>(g_x16 + (size_t)c[i] * D_FEAT + lane * 4);

#pragma unroll
    for (int i = 0; i < EPW; i++) {
        if (r[i] != c[i]) {
            red_add_h2x2(g_sums16 + (size_t)r[i] * D_FEAT + lane * 4, h[i]);
            if (lane == 0) atomicAdd(&g_cnt[r[i]], 1.0f);
        }
    }
}

// ---------------- HMMA GEMM: (mean||x) @ W + bias + row-L2-normalize ---------
// BM=128, BN=256, 512 threads = 16 warps as 4(M)x4(N); warp tile 32x64.
// mma.sync m16n8k16 fp16->f32, single pass. ldmatrix.x4 fragment loads.
// smem rows padded to 272B (136 fp16): conflict-free.
#define BMROWS 128
#define ROWB 272
#define ROWH 136
#define SM_BIAS 0
#define SM_RED  1024
#define SM_A    4096
#define SM_B    (SM_A + BMROWS * ROWB)     // 38912
#define SM_TOT  (SM_B + 256 * ROWB)        // 108544

__device__ __forceinline__ void mma16816(float d[4], const uint32_t a[4], const uint32_t b[2]) {
    asm volatile("mma.sync.aligned.m16n8k16.row.col.f32.f16.f16.f32 "
                 "{%0,%1,%2,%3}, {%4,%5,%6,%7}, {%8,%9}, {%0,%1,%2,%3};"
                 : "+f"(d[0]), "+f"(d[1]), "+f"(d[2]), "+f"(d[3])
                 : "r"(a[0]), "r"(a[1]), "r"(a[2]), "r"(a[3]), "r"(b[0]), "r"(b[1]));
}

__device__ __forceinline__ void ldsm_x4(uint32_t r[4], uint32_t addr) {
    asm volatile("ldmatrix.sync.aligned.m8n8.x4.shared.b16 {%0,%1,%2,%3}, [%4];"
                 : "=r"(r[0]), "=r"(r[1]), "=r"(r[2]), "=r"(r[3]) : "r"(addr));
}

__global__ void __launch_bounds__(512, 1) gemm_hmma_kernel(const float* __restrict__ bias,
                                                           float* __restrict__ out) {
    extern __shared__ __align__(16) unsigned char smem[];
    const uint32_t smb = (uint32_t)__cvta_generic_to_shared(smem);
    const int tid = threadIdx.x;
    const int wid = tid >> 5;
    const int lid = tid & 31;
    const int wm  = wid >> 2;            // 0..3 : rows wm*32..+31
    const int wn  = wid & 3;             // 0..3 : cols wn*64..+63
    const int r4  = lid >> 2;            // 0..7
    const int c4  = lid & 3;             // 0..3
    const int node0 = blockIdx.x * BMROWS;

    // ldmatrix per-lane source rows/k-offsets
    const int a_lrow = (lid & 7) + ((lid & 8)  ? 8 : 0);
    const int a_lko  = (lid & 16) ? 8 : 0;
    const int b_lrow = (lid & 7) + ((lid & 16) ? 8 : 0);
    const int b_lko  = (lid & 8) ? 8 : 0;

    // stage bias
    if (tid < 256) reinterpret_cast<float*>(smem + SM_BIAS)[tid] = bias[tid];

    // A staging role: row = tid>>2 (0..127), k-base = (tid&3)*32 within 128-chunk
    const int arow = tid >> 2;
    const int akb  = (tid & 3) * 32;
    const int amg  = node0 + arow;
    const bool a_ok = (amg < N_NODES);
    const float inv_cnt = a_ok ? (1.0f / fmaxf(g_cnt[amg], 1.0f)) : 0.f;

    float acc[2][8][4];
#pragma unroll
    for (int mt = 0; mt < 2; mt++)
#pragma unroll
        for (int nt = 0; nt < 8; nt++)
#pragma unroll
            for (int q = 0; q < 4; q++) acc[mt][nt][q] = 0.f;

    const uint4* gb = reinterpret_cast<const uint4*>(g_B16_t);

#pragma unroll 1
    for (int c = 0; c < 2; c++) {
        // ---- stage A ----
        if (c == 0) {
            // mean chunk: fp16 sums * inv_cnt -> fp16
            const __half* ssrc = g_sums16 + (size_t)amg * D_FEAT + akb;
            uint32_t byt = (uint32_t)(arow * ROWH + akb) * 2;
#pragma unroll
            for (int j = 0; j < 4; j++) {           // 8 halves per uint4
                uint4 hv = make_uint4(0u, 0u, 0u, 0u);
                if (a_ok) hv = *reinterpret_cast<const uint4*>(ssrc + j * 8);
                __half2* hp = reinterpret_cast<__half2*>(&hv);
#pragma unroll
                for (int t = 0; t < 4; t++) {
                    float2 f = __half22float2(hp[t]);
                    hp[t] = __floats2half2_rn(f.x * inv_cnt, f.y * inv_cnt);
                }
                *reinterpret_cast<uint4*>(smem + SM_A + byt + j * 16) = hv;
            }
        } else {
            // x chunk: straight fp16 copy
            const __half* hx = g_x16 + (size_t)amg * D_FEAT + akb;
            uint32_t byt = (uint32_t)(arow * ROWH + akb) * 2;
#pragma unroll
            for (int j = 0; j < 4; j++) {
                uint4 hv = make_uint4(0u, 0u, 0u, 0u);
                if (a_ok) hv = *reinterpret_cast<const uint4*>(hx + j * 8);
                *reinterpret_cast<uint4*>(smem + SM_A + byt + j * 16) = hv;
            }
        }
        // ---- stage B (coalesced copy of 128-fp16 slices) ----
#pragma unroll
        for (int i = 0; i < 8; i++) {
            int f = i * 512 + tid;           // 0..4095
            int n = f >> 4;
            int j = f & 15;
            *reinterpret_cast<uint4*>(smem + SM_B + n * ROWB + j * 16) = gb[n * 32 + c * 16 + j];
        }
        __syncthreads();

        // ---- compute: 8 k-steps of 16 ----
#pragma unroll
        for (int ks = 0; ks < 8; ks++) {
            const int kb = ks * 16;
            uint32_t af[2][4];
#pragma unroll
            for (int mt = 0; mt < 2; mt++) {
                uint32_t ao = smb + (uint32_t)((wm * 32 + mt * 16 + a_lrow) * ROWH + kb + a_lko) * 2;
                ldsm_x4(af[mt], SM_A + ao);
            }
            uint32_t bf[4][4];
#pragma unroll
            for (int np = 0; np < 4; np++) {
                uint32_t bo = smb + (uint32_t)((wn * 64 + np * 16 + b_lrow) * ROWH + kb + b_lko) * 2;
                ldsm_x4(bf[np], SM_B + bo);
            }
#pragma unroll
            for (int mt = 0; mt < 2; mt++)
#pragma unroll
                for (int nt = 0; nt < 8; nt++)
                    mma16816(acc[mt][nt], af[mt], &bf[nt >> 1][(nt & 1) * 2]);
        }
        __syncthreads();
    }

    // ---- epilogue: + bias, row L2 norm, store ----
    const float* bsm = reinterpret_cast<const float*>(smem + SM_BIAS);
    float ssq[2][2] = {{0.f, 0.f}, {0.f, 0.f}};
#pragma unroll
    for (int mt = 0; mt < 2; mt++)
#pragma unroll
        for (int nt = 0; nt < 8; nt++) {
            int col = wn * 64 + nt * 8 + 2 * c4;
            float b0 = bsm[col], b1 = bsm[col + 1];
            float* d = acc[mt][nt];
            d[0] += b0; d[1] += b1; d[2] += b0; d[3] += b1;
            ssq[mt][0] += d[0] * d[0] + d[1] * d[1];
            ssq[mt][1] += d[2] * d[2] + d[3] * d[3];
        }
#pragma unroll
    for (int off = 1; off <= 2; off <<= 1) {
        ssq[0][0] += __shfl_xor_sync(0xFFFFFFFFu, ssq[0][0], off);
        ssq[0][1] += __shfl_xor_sync(0xFFFFFFFFu, ssq[0][1], off);
        ssq[1][0] += __shfl_xor_sync(0xFFFFFFFFu, ssq[1][0], off);
        ssq[1][1] += __shfl_xor_sync(0xFFFFFFFFu, ssq[1][1], off);
    }
    float* rp = reinterpret_cast<float*>(smem + SM_RED);   // [4 warps_n][128 rows]
    if (c4 == 0) {
#pragma unroll
        for (int mt = 0; mt < 2; mt++)
#pragma unroll
            for (int h = 0; h < 2; h++)
                rp[wn * BMROWS + wm * 32 + mt * 16 + r4 + 8 * h] = ssq[mt][h];
    }
    __syncthreads();

#pragma unroll
    for (int mt = 0; mt < 2; mt++)
#pragma unroll
        for (int h = 0; h < 2; h++) {
            int rr = wm * 32 + mt * 16 + r4 + 8 * h;
            float s = rp[rr] + rp[BMROWS + rr] + rp[2 * BMROWS + rr] + rp[3 * BMROWS + rr];
            float invn = 1.0f / fmaxf(sqrtf(s), 1e-12f);
            int row = node0 + rr;
            if (row < N_NODES) {
#pragma unroll
                for (int nt = 0; nt < 8; nt++) {
                    float* d = acc[mt][nt];
                    float2 o;
                    o.x = d[2 * h]     * invn;
                    o.y = d[2 * h + 1] * invn;
                    *reinterpret_cast<float2*>(out + (size_t)row * C_OUT + wn * 64 + nt * 8 + 2 * c4) = o;
                }
            }
        }
}

// ---------------- launch ------------------------------------------------------
extern "C" void kernel_launch(void* const* d_in, const int* in_sizes, int n_in,
                              void* d_out, int out_size) {
    const float*     x    = (const float*)d_in[0];      // [100000,128]
    const long long* ei   = (const long long*)d_in[1];  // [2,600000]
    const float*     W    = (const float*)d_in[2];      // [256,256]
    const float*     bias = (const float*)d_in[3];      // [1,256]
    float*           out  = (float*)d_out;              // [100000,256]

    init_kernel<<<ZBLKS + XBLKS + 256, 256>>>(x, W, ei);

    {
        long long threads = (long long)(E_EDGES / EPW) * 32;
        scatter_kernel<<<(int)((threads + 255) / 256), 256>>>(ei);
    }

    {
        cudaFuncSetAttribute(gemm_hmma_kernel, cudaFuncAttributeMaxDynamicSharedMemorySize, SM_TOT);
        int grid = (N_NODES + BMROWS - 1) / BMROWS;     // 782
        gemm_hmma_kernel<<<grid, 512, SM_TOT>>>(bias, out);
    }
}

// round 16
// speedup vs baseline: 1.3809x; 1.0808x over previous
#include <cuda_runtime.h>
#include <cuda_fp16.h>
#include <math.h>
#include <stdint.h>

#define N_NODES 100000
#define D_FEAT  128
#define E_EDGES 600000
#define C_OUT   256

// ---------------- scratch (no allocs allowed; __device__ globals) -------------
__device__ __align__(16) __half g_sums16[(size_t)N_NODES * D_FEAT]; // 25.6 MB fp16 accumulators
__device__ __align__(16) __half g_x16[(size_t)N_NODES * D_FEAT];    // 25.6 MB fp16 x image
__device__ float g_cnt[N_NODES];
__device__ int   g_idx64;
__device__ int   g_sep;
// W pre-transposed, fp16: [n][k] rows of 256 fp16 (512B)
__device__ __align__(16) unsigned char g_B16_t[256 * 512];

// ---------------- merged init: zero + x->fp16 + W prep + idx detect ----------
// blocks [0,3125): zero sums16/cnt (2 uint4/thread).
// [3125,9375): convert x (2 float4/thread). [9375,9631): W prep.
#define ZBLKS 3125
#define XBLKS 6250
__global__ void init_kernel(const float* __restrict__ x,
                            const float* __restrict__ W,
                            const long long* __restrict__ ei) {
    if (blockIdx.x < ZBLKS) {
        int i = blockIdx.x * 256 + threadIdx.x;              // 0..800000
        const int HALF = 800000;                             // TOTH4/2
        uint4 z = make_uint4(0u, 0u, 0u, 0u);
        reinterpret_cast<uint4*>(g_sums16)[i]        = z;
        reinterpret_cast<uint4*>(g_sums16)[i + HALF] = z;
        if (i < N_NODES) g_cnt[i] = 0.f;
    } else if (blockIdx.x < ZBLKS + XBLKS) {
        int i = (blockIdx.x - ZBLKS) * 256 + threadIdx.x;    // 0..1.6M
        const int HALF = 1600000;                            // TOT4/2
#pragma unroll
        for (int q = 0; q < 2; q++) {
            int idx = i + q * HALF;
            float4 v = reinterpret_cast<const float4*>(x)[idx];
            __half2 h0 = __floats2half2_rn(v.x, v.y);
            __half2 h1 = __floats2half2_rn(v.z, v.w);
            uint2 pk;
            pk.x = *reinterpret_cast<uint32_t*>(&h0);
            pk.y = *reinterpret_cast<uint32_t*>(&h1);
            reinterpret_cast<uint2*>(g_x16)[idx] = pk;
        }
    } else {
        int k = blockIdx.x - ZBLKS - XBLKS;  // 0..255
        int n = threadIdx.x;                 // 0..255
        float w = W[k * C_OUT + n];
        reinterpret_cast<__half*>(g_B16_t)[n * 256 + k] = __float2half_rn(w);
        if (k == 0 && n == 0) {
            int ok = 1;
#pragma unroll
            for (int i = 0; i < 8; i++) {
                long long v = ei[i];
                if (v < 0 || v >= (long long)N_NODES) ok = 0;
            }
            g_idx64 = ok;
        }
    }
}

// ---------------- separator kernel (profiler alignment; trivial work) ---------
__global__ void sep_kernel() {
    if (threadIdx.x == 0) g_sep = 1;
}

// ---------------- fp16x2 vector reduction ------------------------------------
__device__ __forceinline__ void red_add_h2x2(__half* p, uint2 v) {
    asm volatile("red.global.add.noftz.v2.f16x2 [%0], {%1, %2};"
                 :: "l"(p), "r"(v.x), "r"(v.y) : "memory");
}

// ---------------- edge scatter: 4 edges/warp, pure fp16 gather+RED -----------
#define EPW 4
__global__ void scatter_kernel(const long long* __restrict__ ei) {
    const int warp = (blockIdx.x * blockDim.x + threadIdx.x) >> 5;
    const int lane = threadIdx.x & 31;
    const int e0 = warp * EPW;
    if (e0 >= E_EDGES) return;

    const int use64 = g_idx64;
    int r[EPW], c[EPW];
#pragma unroll
    for (int i = 0; i < EPW; i++) {
        int e = e0 + i;                      // E_EDGES % EPW == 0
        if (use64) {
            r[i] = (int)ei[e];
            c[i] = (int)ei[E_EDGES + e];
        } else {
            const int* p = (const int*)ei;
            r[i] = p[e];
            c[i] = p[E_EDGES + e];
        }
    }

    uint2 h[EPW];
#pragma unroll
    for (int i = 0; i < EPW; i++)
        if (r[i] != c[i])
            h[i] = *reinterpret_cast<const uint2*>(g_x16 + (size_t)c[i] * D_FEAT + lane * 4);

#pragma unroll
    for (int i = 0; i < EPW; i++) {
        if (r[i] != c[i]) {
            red_add_h2x2(g_sums16 + (size_t)r[i] * D_FEAT + lane * 4, h[i]);
            if (lane == 0) atomicAdd(&g_cnt[r[i]], 1.0f);
        }
    }
}

// ---------------- persistent HMMA GEMM: B smem-resident ----------------------
// grid=152 persistent CTAs; each loops node tiles t, t+152, ... of 782.
// BM=128, BN=256, 512 threads = 16 warps as 4(M)x4(N); warp tile 32x64.
// mma.sync m16n8k16 fp16->f32, single pass. ldmatrix.x4.
// smem rows padded to 272B (136 fp16): conflict-free.
#define BMROWS 128
#define NTILES ((N_NODES + BMROWS - 1) / BMROWS)   // 782
#define NPCTAS 152
#define ROWB 272
#define ROWH 136
#define ACHUNK (BMROWS * ROWB)             // 34816
#define BCHUNK (256 * ROWB)                // 69632
#define SM_BIAS 0
#define SM_RED  1024
#define SM_A    4096
#define SM_B    (SM_A + 2 * ACHUNK)        // 73728
#define SM_TOT  (SM_B + 2 * BCHUNK)        // 212992

__device__ __forceinline__ void mma16816(float d[4], const uint32_t a[4], const uint32_t b[2]) {
    asm volatile("mma.sync.aligned.m16n8k16.row.col.f32.f16.f16.f32 "
                 "{%0,%1,%2,%3}, {%4,%5,%6,%7}, {%8,%9}, {%0,%1,%2,%3};"
                 : "+f"(d[0]), "+f"(d[1]), "+f"(d[2]), "+f"(d[3])
                 : "r"(a[0]), "r"(a[1]), "r"(a[2]), "r"(a[3]), "r"(b[0]), "r"(b[1]));
}

__device__ __forceinline__ void ldsm_x4(uint32_t r[4], uint32_t addr) {
    asm volatile("ldmatrix.sync.aligned.m8n8.x4.shared.b16 {%0,%1,%2,%3}, [%4];"
                 : "=r"(r[0]), "=r"(r[1]), "=r"(r[2]), "=r"(r[3]) : "r"(addr));
}

__global__ void __launch_bounds__(512, 1) gemm_hmma_kernel(const float* __restrict__ bias,
                                                           float* __restrict__ out) {
    extern __shared__ __align__(16) unsigned char smem[];
    const uint32_t smb = (uint32_t)__cvta_generic_to_shared(smem);
    const int tid = threadIdx.x;
    const int lid = tid & 31;
    const int wid = tid >> 5;
    const int wm  = wid >> 2;            // 0..3 : rows wm*32..+31
    const int wn  = wid & 3;             // 0..3 : cols wn*64..+63
    const int r4  = lid >> 2;            // 0..7
    const int c4  = lid & 3;             // 0..3

    // ldmatrix per-lane source rows/k-offsets
    const int a_lrow = (lid & 7) + ((lid & 8)  ? 8 : 0);
    const int a_lko  = (lid & 16) ? 8 : 0;
    const int b_lrow = (lid & 7) + ((lid & 16) ? 8 : 0);
    const int b_lko  = (lid & 8) ? 8 : 0;

    // A staging role: row = tid>>2 (0..127), k-base = (tid&3)*32 within chunk
    const int arow = tid >> 2;
    const int akb  = (tid & 3) * 32;

    // ---- one-time staging: bias + full B (both chunks) ----
    if (tid < 256) reinterpret_cast<float*>(smem + SM_BIAS)[tid] = bias[tid];
    {
        const uint4* gb = reinterpret_cast<const uint4*>(g_B16_t);
#pragma unroll
        for (int c = 0; c < 2; c++)
#pragma unroll
            for (int i = 0; i < 8; i++) {
                int f = i * 512 + tid;       // 0..4095
                int n = f >> 4;
                int j = f & 15;
                *reinterpret_cast<uint4*>(smem + SM_B + c * BCHUNK + n * ROWB + j * 16)
                    = gb[n * 32 + c * 16 + j];
            }
    }
    const float* bsm = reinterpret_cast<const float*>(smem + SM_BIAS);
    float* rp = reinterpret_cast<float*>(smem + SM_RED);   // [4 warps_n][128 rows]

    // ---- persistent tile loop ----
    for (int t = blockIdx.x; t < NTILES; t += NPCTAS) {
        const int node0 = t * BMROWS;
        const int amg   = node0 + arow;
        const bool a_ok = (amg < N_NODES);
        const float inv_cnt = a_ok ? (1.0f / fmaxf(g_cnt[amg], 1.0f)) : 0.f;

        // ---- stage A (both chunks) ----
        {
            // chunk 0: mean = fp16 sums * inv_cnt
            const __half* ssrc = g_sums16 + (size_t)amg * D_FEAT + akb;
            uint32_t byt = (uint32_t)(arow * ROWH + akb) * 2;
#pragma unroll
            for (int j = 0; j < 4; j++) {
                uint4 hv = make_uint4(0u, 0u, 0u, 0u);
                if (a_ok) hv = *reinterpret_cast<const uint4*>(ssrc + j * 8);
                __half2* hp = reinterpret_cast<__half2*>(&hv);
#pragma unroll
                for (int q = 0; q < 4; q++) {
                    float2 f = __half22float2(hp[q]);
                    hp[q] = __floats2half2_rn(f.x * inv_cnt, f.y * inv_cnt);
                }
                *reinterpret_cast<uint4*>(smem + SM_A + byt + j * 16) = hv;
            }
            // chunk 1: straight fp16 copy of x
            const __half* hx = g_x16 + (size_t)amg * D_FEAT + akb;
#pragma unroll
            for (int j = 0; j < 4; j++) {
                uint4 hv = make_uint4(0u, 0u, 0u, 0u);
                if (a_ok) hv = *reinterpret_cast<const uint4*>(hx + j * 8);
                *reinterpret_cast<uint4*>(smem + SM_A + ACHUNK + byt + j * 16) = hv;
            }
        }
        __syncthreads();

        // ---- compute: 2 chunks x 8 k-steps ----
        float acc[2][8][4];
#pragma unroll
        for (int mt = 0; mt < 2; mt++)
#pragma unroll
            for (int nt = 0; nt < 8; nt++)
#pragma unroll
                for (int q = 0; q < 4; q++) acc[mt][nt][q] = 0.f;

#pragma unroll
        for (int c = 0; c < 2; c++) {
            const uint32_t abase = smb + SM_A + c * ACHUNK;
            const uint32_t bbase = smb + SM_B + c * BCHUNK;
#pragma unroll
            for (int ks = 0; ks < 8; ks++) {
                const int kb = ks * 16;
                uint32_t af[2][4];
#pragma unroll
                for (int mt = 0; mt < 2; mt++) {
                    uint32_t ao = abase + (uint32_t)((wm * 32 + mt * 16 + a_lrow) * ROWH + kb + a_lko) * 2;
                    ldsm_x4(af[mt], ao);
                }
                uint32_t bf[4][4];
#pragma unroll
                for (int np = 0; np < 4; np++) {
                    uint32_t bo = bbase + (uint32_t)((wn * 64 + np * 16 + b_lrow) * ROWH + kb + b_lko) * 2;
                    ldsm_x4(bf[np], bo);
                }
#pragma unroll
                for (int mt = 0; mt < 2; mt++)
#pragma unroll
                    for (int nt = 0; nt < 8; nt++)
                        mma16816(acc[mt][nt], af[mt], &bf[nt >> 1][(nt & 1) * 2]);
            }
        }

        // ---- epilogue: + bias, row L2 norm, store ----
        float ssq[2][2] = {{0.f, 0.f}, {0.f, 0.f}};
#pragma unroll
        for (int mt = 0; mt < 2; mt++)
#pragma unroll
            for (int nt = 0; nt < 8; nt++) {
                int col = wn * 64 + nt * 8 + 2 * c4;
                float b0 = bsm[col], b1 = bsm[col + 1];
                float* d = acc[mt][nt];
                d[0] += b0; d[1] += b1; d[2] += b0; d[3] += b1;
                ssq[mt][0] += d[0] * d[0] + d[1] * d[1];
                ssq[mt][1] += d[2] * d[2] + d[3] * d[3];
            }
#pragma unroll
        for (int off = 1; off <= 2; off <<= 1) {
            ssq[0][0] += __shfl_xor_sync(0xFFFFFFFFu, ssq[0][0], off);
            ssq[0][1] += __shfl_xor_sync(0xFFFFFFFFu, ssq[0][1], off);
            ssq[1][0] += __shfl_xor_sync(0xFFFFFFFFu, ssq[1][0], off);
            ssq[1][1] += __shfl_xor_sync(0xFFFFFFFFu, ssq[1][1], off);
        }
        if (c4 == 0) {
#pragma unroll
            for (int mt = 0; mt < 2; mt++)
#pragma unroll
                for (int h = 0; h < 2; h++)
                    rp[wn * BMROWS + wm * 32 + mt * 16 + r4 + 8 * h] = ssq[mt][h];
        }
        __syncthreads();

#pragma unroll
        for (int mt = 0; mt < 2; mt++)
#pragma unroll
            for (int h = 0; h < 2; h++) {
                int rr = wm * 32 + mt * 16 + r4 + 8 * h;
                float s = rp[rr] + rp[BMROWS + rr] + rp[2 * BMROWS + rr] + rp[3 * BMROWS + rr];
                float invn = 1.0f / fmaxf(sqrtf(s), 1e-12f);
                int row = node0 + rr;
                if (row < N_NODES) {
#pragma unroll
                    for (int nt = 0; nt < 8; nt++) {
                        float* d = acc[mt][nt];
                        float2 o;
                        o.x = d[2 * h]     * invn;
                        o.y = d[2 * h + 1] * invn;
                        *reinterpret_cast<float2*>(out + (size_t)row * C_OUT + wn * 64 + nt * 8 + 2 * c4) = o;
                    }
                }
            }
        __syncthreads();   // protect A smem + rp before next tile overwrites
    }
}

// ---------------- launch ------------------------------------------------------
extern "C" void kernel_launch(void* const* d_in, const int* in_sizes, int n_in,
                              void* d_out, int out_size) {
    const float*     x    = (const float*)d_in[0];      // [100000,128]
    const long long* ei   = (const long long*)d_in[1];  // [2,600000]
    const float*     W    = (const float*)d_in[2];      // [256,256]
    const float*     bias = (const float*)d_in[3];      // [1,256]
    float*           out  = (float*)d_out;              // [100000,256]

    init_kernel<<<ZBLKS + XBLKS + 256, 256>>>(x, W, ei);

    {
        long long threads = (long long)(E_EDGES / EPW) * 32;
        scatter_kernel<<<(int)((threads + 255) / 256), 256>>>(ei);
    }

    sep_kernel<<<1, 32>>>();   // launch #3: aligns ncu capture onto the GEMM

    {
        cudaFuncSetAttribute(gemm_hmma_kernel, cudaFuncAttributeMaxDynamicSharedMemorySize, SM_TOT);
        gemm_hmma_kernel<<<NPCTAS, 512, SM_TOT>>>(bias, out);
    }
}

// round 17
// speedup vs baseline: 1.4002x; 1.0140x over previous
#include <cuda_runtime.h>
#include <cuda_fp16.h>
#include <math.h>
#include <stdint.h>

#define N_NODES 100000
#define D_FEAT  128
#define E_EDGES 600000
#define C_OUT   256

// ---------------- scratch (no allocs allowed; __device__ globals) -------------
__device__ __align__(16) __half g_sums16[(size_t)N_NODES * D_FEAT]; // 25.6 MB fp16 accumulators
__device__ __align__(16) __half g_x16[(size_t)N_NODES * D_FEAT];    // 25.6 MB fp16 x image
__device__ float g_cnt[N_NODES];
__device__ int   g_idx64;
__device__ int   g_sep;
// W pre-transposed, fp16: [n][k] rows of 256 fp16 (512B)
__device__ __align__(16) unsigned char g_B16_t[256 * 512];

// ---------------- merged init: zero + x->fp16 + W prep + idx detect ----------
#define ZBLKS 3125
#define XBLKS 6250
__global__ void init_kernel(const float* __restrict__ x,
                            const float* __restrict__ W,
                            const long long* __restrict__ ei) {
    if (blockIdx.x < ZBLKS) {
        int i = blockIdx.x * 256 + threadIdx.x;              // 0..800000
        const int HALF = 800000;
        uint4 z = make_uint4(0u, 0u, 0u, 0u);
        reinterpret_cast<uint4*>(g_sums16)[i]        = z;
        reinterpret_cast<uint4*>(g_sums16)[i + HALF] = z;
        if (i < N_NODES) g_cnt[i] = 0.f;
    } else if (blockIdx.x < ZBLKS + XBLKS) {
        int i = (blockIdx.x - ZBLKS) * 256 + threadIdx.x;
        const int HALF = 1600000;
#pragma unroll
        for (int q = 0; q < 2; q++) {
            int idx = i + q * HALF;
            float4 v = reinterpret_cast<const float4*>(x)[idx];
            __half2 h0 = __floats2half2_rn(v.x, v.y);
            __half2 h1 = __floats2half2_rn(v.z, v.w);
            uint2 pk;
            pk.x = *reinterpret_cast<uint32_t*>(&h0);
            pk.y = *reinterpret_cast<uint32_t*>(&h1);
            reinterpret_cast<uint2*>(g_x16)[idx] = pk;
        }
    } else {
        int k = blockIdx.x - ZBLKS - XBLKS;  // 0..255
        int n = threadIdx.x;                 // 0..255
        float w = W[k * C_OUT + n];
        reinterpret_cast<__half*>(g_B16_t)[n * 256 + k] = __float2half_rn(w);
        if (k == 0 && n == 0) {
            int ok = 1;
#pragma unroll
            for (int i = 0; i < 8; i++) {
                long long v = ei[i];
                if (v < 0 || v >= (long long)N_NODES) ok = 0;
            }
            g_idx64 = ok;
        }
    }
}

// ---------------- separator kernel (profiler alignment) -----------------------
__global__ void sep_kernel() {
    if (threadIdx.x == 0) g_sep = 1;
}

// ---------------- fp16x2 vector reduction ------------------------------------
__device__ __forceinline__ void red_add_h2x2(__half* p, uint2 v) {
    asm volatile("red.global.add.noftz.v2.f16x2 [%0], {%1, %2};"
                 :: "l"(p), "r"(v.x), "r"(v.y) : "memory");
}

// ---------------- edge scatter: 4 edges/warp, pure fp16 gather+RED -----------
#define EPW 4
__global__ void scatter_kernel(const long long* __restrict__ ei) {
    const int warp = (blockIdx.x * blockDim.x + threadIdx.x) >> 5;
    const int lane = threadIdx.x & 31;
    const int e0 = warp * EPW;
    if (e0 >= E_EDGES) return;

    const int use64 = g_idx64;
    int r[EPW], c[EPW];
#pragma unroll
    for (int i = 0; i < EPW; i++) {
        int e = e0 + i;                      // E_EDGES % EPW == 0
        if (use64) {
            r[i] = (int)ei[e];
            c[i] = (int)ei[E_EDGES + e];
        } else {
            const int* p = (const int*)ei;
            r[i] = p[e];
            c[i] = p[E_EDGES + e];
        }
    }

    uint2 h[EPW];
#pragma unroll
    for (int i = 0; i < EPW; i++)
        if (r[i] != c[i])
            h[i] = *reinterpret_cast<const uint2*>(g_x16 + (size_t)c[i] * D_FEAT + lane * 4);

#pragma unroll
    for (int i = 0; i < EPW; i++) {
        if (r[i] != c[i]) {
            red_add_h2x2(g_sums16 + (size_t)r[i] * D_FEAT + lane * 4, h[i]);
            if (lane == 0) atomicAdd(&g_cnt[r[i]], 1.0f);
        }
    }
}

// ---------------- persistent pipelined HMMA GEMM ------------------------------
// grid=152 persistent CTAs; each loops node tiles of 64 rows (1563 tiles).
// 512 threads = 16 warps as 2(M)x8(N); warp tile 32x32.
// A: raw fp16 sums & x chunks staged via cp.async, double-buffered.
// Mean division moved to epilogue: out = accS*inv_cnt + accX + bias, then L2 norm.
// smem rows padded to 272B (136 fp16): conflict-free ldmatrix.
#define BMROWS 64
#define NTILES ((N_NODES + BMROWS - 1) / BMROWS)   // 1563
#define NPCTAS 152
#define ROWB 272
#define ROWH 136
#define ACH (BMROWS * ROWB)                // 17408 per chunk
#define BCHUNK (256 * ROWB)                // 69632
#define SM_BIAS 0
#define SM_RED  1024                       // 8 n-warps x 64 rows x 4B = 2048
#define SM_A    4096                       // 4 chunk buffers: [buf][chunk]
#define SM_B    (SM_A + 4 * ACH)           // 73728
#define SM_TOT  (SM_B + 2 * BCHUNK)        // 212992

__device__ __forceinline__ void mma16816(float d[4], const uint32_t a[4], const uint32_t b[2]) {
    asm volatile("mma.sync.aligned.m16n8k16.row.col.f32.f16.f16.f32 "
                 "{%0,%1,%2,%3}, {%4,%5,%6,%7}, {%8,%9}, {%0,%1,%2,%3};"
                 : "+f"(d[0]), "+f"(d[1]), "+f"(d[2]), "+f"(d[3])
                 : "r"(a[0]), "r"(a[1]), "r"(a[2]), "r"(a[3]), "r"(b[0]), "r"(b[1]));
}

__device__ __forceinline__ void ldsm_x4(uint32_t r[4], uint32_t addr) {
    asm volatile("ldmatrix.sync.aligned.m8n8.x4.shared.b16 {%0,%1,%2,%3}, [%4];"
                 : "=r"(r[0]), "=r"(r[1]), "=r"(r[2]), "=r"(r[3]) : "r"(addr));
}

__device__ __forceinline__ void cp_async16(uint32_t dst, const void* src, int sz) {
    asm volatile("cp.async.cg.shared.global [%0], [%1], 16, %2;"
                 :: "r"(dst), "l"(src), "r"(sz) : "memory");
}
#define CP_COMMIT() asm volatile("cp.async.commit_group;" ::: "memory")
#define CP_WAIT0()  asm volatile("cp.async.wait_group 0;" ::: "memory")

__global__ void __launch_bounds__(512, 1) gemm_hmma_kernel(const float* __restrict__ bias,
                                                           float* __restrict__ out) {
    extern __shared__ __align__(16) unsigned char smem[];
    const uint32_t smb = (uint32_t)__cvta_generic_to_shared(smem);
    const int tid = threadIdx.x;
    const int lid = tid & 31;
    const int wid = tid >> 5;
    const int wm  = wid >> 3;            // 0..1 : rows wm*32..+31
    const int wn  = wid & 7;             // 0..7 : cols wn*32..+31
    const int r4  = lid >> 2;            // 0..7
    const int c4  = lid & 3;             // 0..3

    // ldmatrix per-lane source rows/k-offsets (x4 fragment layout)
    const int a_lrow = (lid & 7) + ((lid & 8)  ? 8 : 0);
    const int a_lko  = (lid & 16) ? 8 : 0;
    const int b_lrow = (lid & 7) + ((lid & 16) ? 8 : 0);
    const int b_lko  = (lid & 8) ? 8 : 0;

    // ---- one-time staging: bias + full B ----
    if (tid < 256) reinterpret_cast<float*>(smem + SM_BIAS)[tid] = bias[tid];
    {
        const uint4* gb = reinterpret_cast<const uint4*>(g_B16_t);
#pragma unroll
        for (int c = 0; c < 2; c++)
#pragma unroll
            for (int i = 0; i < 8; i++) {
                int f = i * 512 + tid;       // 0..4095
                int n = f >> 4;
                int j = f & 15;
                *reinterpret_cast<uint4*>(smem + SM_B + c * BCHUNK + n * ROWB + j * 16)
                    = gb[n * 32 + c * 16 + j];
            }
    }
    const float* bsm = reinterpret_cast<const float*>(smem + SM_BIAS);
    float* rp = reinterpret_cast<float*>(smem + SM_RED);   // [8 n-warps][64 rows]

    // A stage via cp.async: 4 x 16B per thread covers 2 chunks x 64 rows x 256B
    auto stage_A = [&](int t, int buf) {
#pragma unroll
        for (int q = 0; q < 4; q++) {
            int f     = q * 512 + tid;       // 0..2047
            int chunk = f >> 10;
            int row   = (f >> 4) & 63;
            int j     = f & 15;
            int grow  = t * BMROWS + row;
            int ok    = (grow < N_NODES);
            int srow  = ok ? grow : (N_NODES - 1);
            const __half* src = (chunk ? g_x16 : g_sums16) + (size_t)srow * D_FEAT + j * 8;
            uint32_t dst = smb + SM_A + (buf * 2 + chunk) * ACH + row * ROWB + j * 16;
            cp_async16(dst, src, ok ? 16 : 0);
        }
    };

    // ---- prologue: stage first tile ----
    if (blockIdx.x < NTILES) stage_A(blockIdx.x, 0);
    CP_COMMIT();
    CP_WAIT0();
    __syncthreads();

    int buf = 0;
    for (int t = blockIdx.x; t < NTILES; t += NPCTAS) {
        const int node0 = t * BMROWS;
        const int tn = t + NPCTAS;
        if (tn < NTILES) stage_A(tn, buf ^ 1);
        CP_COMMIT();

        // ---- compute: accS (sums chunk), accX (x chunk) ----
        float accS[2][4][4], accX[2][4][4];
#pragma unroll
        for (int mt = 0; mt < 2; mt++)
#pragma unroll
            for (int nt = 0; nt < 4; nt++)
#pragma unroll
                for (int q = 0; q < 4; q++) { accS[mt][nt][q] = 0.f; accX[mt][nt][q] = 0.f; }

#pragma unroll
        for (int c = 0; c < 2; c++) {
            const uint32_t abase = smb + SM_A + (buf * 2 + c) * ACH;
            const uint32_t bbase = smb + SM_B + c * BCHUNK;
            float (*acc)[4][4] = c ? accX : accS;
#pragma unroll
            for (int ks = 0; ks < 8; ks++) {
                const int kb = ks * 16;
                uint32_t af[2][4];
#pragma unroll
                for (int mt = 0; mt < 2; mt++) {
                    uint32_t ao = abase + (uint32_t)((wm * 32 + mt * 16 + a_lrow) * ROWH + kb + a_lko) * 2;
                    ldsm_x4(af[mt], ao);
                }
                uint32_t bf[2][4];
#pragma unroll
                for (int np = 0; np < 2; np++) {
                    uint32_t bo = bbase + (uint32_t)((wn * 32 + np * 16 + b_lrow) * ROWH + kb + b_lko) * 2;
                    ldsm_x4(bf[np], bo);
                }
#pragma unroll
                for (int mt = 0; mt < 2; mt++)
#pragma unroll
                    for (int nt = 0; nt < 4; nt++)
                        mma16816(acc[mt][nt], af[mt], &bf[nt >> 1][(nt & 1) * 2]);
            }
        }

        // ---- epilogue: d = accS*inv_cnt + accX + bias; row L2 norm; store ----
        float invc[2][2];
#pragma unroll
        for (int mt = 0; mt < 2; mt++)
#pragma unroll
            for (int h = 0; h < 2; h++) {
                int row = node0 + wm * 32 + mt * 16 + r4 + 8 * h;
                invc[mt][h] = (row < N_NODES) ? (1.0f / fmaxf(g_cnt[row], 1.0f)) : 0.f;
            }

        float ssq[2][2] = {{0.f, 0.f}, {0.f, 0.f}};
#pragma unroll
        for (int mt = 0; mt < 2; mt++)
#pragma unroll
            for (int nt = 0; nt < 4; nt++) {
                int col = wn * 32 + nt * 8 + 2 * c4;
                float b0 = bsm[col], b1 = bsm[col + 1];
                float* s = accS[mt][nt];
                float* xx = accX[mt][nt];
                s[0] = s[0] * invc[mt][0] + xx[0] + b0;
                s[1] = s[1] * invc[mt][0] + xx[1] + b1;
                s[2] = s[2] * invc[mt][1] + xx[2] + b0;
                s[3] = s[3] * invc[mt][1] + xx[3] + b1;
                ssq[mt][0] += s[0] * s[0] + s[1] * s[1];
                ssq[mt][1] += s[2] * s[2] + s[3] * s[3];
            }
#pragma unroll
        for (int off = 1; off <= 2; off <<= 1) {
            ssq[0][0] += __shfl_xor_sync(0xFFFFFFFFu, ssq[0][0], off);
            ssq[0][1] += __shfl_xor_sync(0xFFFFFFFFu, ssq[0][1], off);
            ssq[1][0] += __shfl_xor_sync(0xFFFFFFFFu, ssq[1][0], off);
            ssq[1][1] += __shfl_xor_sync(0xFFFFFFFFu, ssq[1][1], off);
        }
        if (c4 == 0) {
#pragma unroll
            for (int mt = 0; mt < 2; mt++)
#pragma unroll
                for (int h = 0; h < 2; h++)
                    rp[wn * BMROWS + wm * 32 + mt * 16 + r4 + 8 * h] = ssq[mt][h];
        }
        __syncthreads();

#pragma unroll
        for (int mt = 0; mt < 2; mt++)
#pragma unroll
            for (int h = 0; h < 2; h++) {
                int rr = wm * 32 + mt * 16 + r4 + 8 * h;
                float s = 0.f;
#pragma unroll
                for (int w = 0; w < 8; w++) s += rp[w * BMROWS + rr];
                float invn = 1.0f / fmaxf(sqrtf(s), 1e-12f);
                int row = node0 + rr;
                if (row < N_NODES) {
#pragma unroll
                    for (int nt = 0; nt < 4; nt++) {
                        float* d = accS[mt][nt];
                        float2 o;
                        o.x = d[2 * h]     * invn;
                        o.y = d[2 * h + 1] * invn;
                        *reinterpret_cast<float2*>(out + (size_t)row * C_OUT + wn * 32 + nt * 8 + 2 * c4) = o;
                    }
                }
            }

        CP_WAIT0();
        __syncthreads();
        buf ^= 1;
    }
}

// ---------------- launch ------------------------------------------------------
extern "C" void kernel_launch(void* const* d_in, const int* in_sizes, int n_in,
                              void* d_out, int out_size) {
    const float*     x    = (const float*)d_in[0];      // [100000,128]
    const long long* ei   = (const long long*)d_in[1];  // [2,600000]
    const float*     W    = (const float*)d_in[2];      // [256,256]
    const float*     bias = (const float*)d_in[3];      // [1,256]
    float*           out  = (float*)d_out;              // [100000,256]

    init_kernel<<<ZBLKS + XBLKS + 256, 256>>>(x, W, ei);

    {
        long long threads = (long long)(E_EDGES / EPW) * 32;
        scatter_kernel<<<(int)((threads + 255) / 256), 256>>>(ei);
    }

    sep_kernel<<<1, 32>>>();   // launch #3: aligns ncu capture onto the GEMM

    {
        cudaFuncSetAttribute(gemm_hmma_kernel, cudaFuncAttributeMaxDynamicSharedMemorySize, SM_TOT);
        gemm_hmma_kernel<<<NPCTAS, 512, SM_TOT>>>(bias, out);
    }
}